// round 4
// baseline (speedup 1.0000x reference)
#include <cuda_runtime.h>
#include <cstdint>

#define BB 16
#define DD 128
#define MM 4096
#define VV 32000
#define BM (BB*MM)

// ---------------- scratch (static device globals; no allocation) ----------------
__device__ __align__(16) float g_u[BB*DD];   // current query u  [B][D]
__device__ __align__(16) float g_t[BB*VV];   // score table t[b][v] = C_h[v].u[b]
__device__ __align__(16) float g_w[BB*VV];   // scattered (unnormalized) exp weights
__device__ float g_sum[BB];                  // softmax denominators
__device__ int g_is64;                       // story dtype flag (1 if int64)

// ---------------- helpers ----------------
__device__ __forceinline__ int4 load_toks(const int* __restrict__ story, int idx) {
    if (!g_is64) {
        return ((const int4*)story)[idx];
    } else {
        longlong4 l = ((const longlong4*)story)[idx];
        return make_int4((int)l.x, (int)l.y, (int)l.z, (int)l.w);
    }
}

__device__ __forceinline__ uint64_t packf2(float x, float y) {
    uint64_t r;
    asm("mov.b64 %0, {%1, %2};" : "=l"(r) : "f"(x), "f"(y));
    return r;
}
__device__ __forceinline__ void unpackf2(uint64_t v, float& x, float& y) {
    asm("mov.b64 {%0, %1}, %2;" : "=f"(x), "=f"(y) : "l"(v));
}
// packed dual-FMA: acc.{lo,hi} += a.{lo,hi} * b.{lo,hi}
__device__ __forceinline__ void ffma2(uint64_t& acc, uint64_t a, uint64_t b) {
    asm("fma.rn.f32x2 %0, %1, %2, %0;" : "+l"(acc) : "l"(a), "l"(b));
}

// ---------------- kernels ----------------

// t[b][v] = dot(C_h[v], u[b]) for all v,b.
// Grid MUST be 2000 x 128: block covers 16 rows, each warp exactly 4 rows.
// Lane layout: lane = b*2 + half; lane computes half-dot (64 dims) for its b.
// FIRST : also init g_u = uin(q) and detect story dtype
// ZERO_W: also zero g_w/g_sum for the following scatter pass
// COPY_U: block 0 additionally copies g_u (== u1) to u_out
// USE_GU: read u from g_u instead of the uin parameter
template <bool FIRST, bool ZERO_W, bool COPY_U, bool USE_GU>
__global__ void __launch_bounds__(128) k_dot(const float* __restrict__ Ch,
                                             const float* __restrict__ uin,
                                             float* __restrict__ u_out,
                                             const int* __restrict__ story) {
    if (ZERO_W) {
        int j = blockIdx.x*128 + threadIdx.x;          // 256000 threads >= 128000 float4
        if (j < BB*VV/4) ((float4*)g_w)[j] = make_float4(0.f, 0.f, 0.f, 0.f);
        if (blockIdx.x == 0 && threadIdx.x < BB) g_sum[threadIdx.x] = 0.f;
    }
    if (FIRST && blockIdx.x == 0) {
        for (int j = threadIdx.x; j < BB*DD; j += 128) g_u[j] = uin[j];
        if (threadIdx.x == 0) {
            // int64 little-endian: odd words are high words of small tokens -> 0
            int z = story[1] | story[3] | story[5] | story[7];
            g_is64 = (z == 0) ? 1 : 0;
        }
    }
    if (COPY_U && blockIdx.x == 0) {
        for (int j = threadIdx.x; j < BB*DD; j += 128) u_out[j] = g_u[j];
    }

    // 4 warps x 4 rows x 34 slots (skip slot at mid-row kills the half-vs-half
    // bank conflict on the broadcast reads)
    __shared__ ulonglong2 rowbuf[4][4][34];

    const int warp = threadIdx.x >> 5;
    const int lane = threadIdx.x & 31;
    const int b    = lane >> 1;
    const int half = lane & 1;
    const int slot = lane + (lane >> 4);

    // pack this lane's u-half: 64 floats -> 32 packed u64
    uint64_t ureg[32];
    {
        const float4* u4 = USE_GU ? (const float4*)g_u : (const float4*)uin;
        #pragma unroll
        for (int j = 0; j < 16; j++) {
            float4 uu = u4[b*32 + half*16 + j];
            ureg[2*j]   = packf2(uu.x, uu.y);
            ureg[2*j+1] = packf2(uu.z, uu.w);
        }
    }

    const int v0 = blockIdx.x*16 + warp*4;

    // front-batched row loads (MLP=4), coalesced 512B per row
    #pragma unroll
    for (int r = 0; r < 4; r++) {
        float4 rv = ((const float4*)(Ch + (size_t)(v0 + r) * DD))[lane];
        rowbuf[warp][r][slot] = make_ulonglong2(packf2(rv.x, rv.y), packf2(rv.z, rv.w));
    }
    __syncwarp();

    #pragma unroll
    for (int r = 0; r < 4; r++) {
        uint64_t a0 = packf2(0.f, 0.f);
        uint64_t a1 = packf2(0.f, 0.f);
        const ulonglong2* rb = &rowbuf[warp][r][half*17];
        #pragma unroll
        for (int j = 0; j < 16; j++) {
            ulonglong2 c = rb[j];                      // LDS.128, broadcast x16
            ffma2(a0, c.x, ureg[2*j]);
            ffma2(a1, c.y, ureg[2*j+1]);
        }
        float x0, x1, x2, x3;
        unpackf2(a0, x0, x1);
        unpackf2(a1, x2, x3);
        float s = (x0 + x1) + (x2 + x3);
        s += __shfl_down_sync(0xffffffffu, s, 1);      // partner half
        if (half == 0) g_t[b*VV + v0 + r] = s;
    }
}

// Fused attention: logits -> exp (no max shift; logits are O(10) by construction)
// -> scatter unnormalized e into g_w, accumulate per-b sum via one block atomic.
__global__ void __launch_bounds__(256) k_att(const int* __restrict__ story) {
    const int i = blockIdx.x*256 + threadIdx.x;
    const int b = i >> 12;
    int4 tk = load_toks(story, i);
    const float* tb = g_t + b*VV;
    float val = tb[tk.x] + tb[tk.y] + tb[tk.z] + tb[tk.w];
    float e = __expf(val);

    float s = e;
    #pragma unroll
    for (int o = 16; o; o >>= 1) s += __shfl_xor_sync(0xffffffffu, s, o);
    __shared__ float sw[8];
    const int lane = threadIdx.x & 31, wid = threadIdx.x >> 5;
    if (lane == 0) sw[wid] = s;
    __syncthreads();
    if (threadIdx.x == 0) {
        float t = 0.f;
        #pragma unroll
        for (int k = 0; k < 8; k++) t += sw[k];
        atomicAdd(&g_sum[b], t);
    }

    float* wb = g_w + b*VV;
    atomicAdd(&wb[tk.x], e);
    atomicAdd(&wb[tk.y], e);
    atomicAdd(&wb[tk.z], e);
    atomicAdd(&wb[tk.w], e);
}

// u[b][d] += sum_v (w[b][v]/sum[b]) * C_next[v][d]
// 500 blocks x 256 threads; block covers UVC=64 vocab rows for all 16 b.
#define UVC 64
__global__ void __launch_bounds__(256) k_update(const float* __restrict__ Cn) {
    __shared__ __align__(16) float wsh[BB][UVC];
    __shared__ float sinv[BB];
    const int tid = threadIdx.x;
    const int d   = tid & 127;
    const int b0  = (tid >> 7) * 8;
    const int v0  = blockIdx.x * UVC;

    if (tid < BB) sinv[tid] = 1.0f / g_sum[tid];
    __syncthreads();
    #pragma unroll
    for (int j = tid; j < BB*UVC; j += 256) {
        int b = j >> 6, vi = j & (UVC-1);
        wsh[b][vi] = g_w[b*VV + v0 + vi] * sinv[b];
    }
    __syncthreads();

    float acc[8];
    #pragma unroll
    for (int b = 0; b < 8; b++) acc[b] = 0.f;

    const float* base = Cn + (size_t)v0 * DD + d;

    #pragma unroll 2
    for (int vi4 = 0; vi4 < UVC/4; vi4++) {
        float c0 = base[(size_t)(vi4*4 + 0) * DD];
        float c1 = base[(size_t)(vi4*4 + 1) * DD];
        float c2 = base[(size_t)(vi4*4 + 2) * DD];
        float c3 = base[(size_t)(vi4*4 + 3) * DD];
        #pragma unroll
        for (int b = 0; b < 8; b++) {
            float4 w = ((const float4*)wsh[b0 + b])[vi4];
            acc[b] += w.x*c0;
            acc[b] += w.y*c1;
            acc[b] += w.z*c2;
            acc[b] += w.w*c3;
        }
    }

    #pragma unroll
    for (int b = 0; b < 8; b++)
        atomicAdd(&g_u[(b0 + b)*DD + d], acc[b]);
}

// final-hop logits straight to output
__global__ void __launch_bounds__(256) k_logits_out(const int* __restrict__ story,
                                                    float* __restrict__ out) {
    const int i = blockIdx.x*256 + threadIdx.x;
    const int b = i >> 12;
    int4 tk = load_toks(story, i);
    const float* tb = g_t + b*VV;
    out[i] = tb[tk.x] + tb[tk.y] + tb[tk.z] + tb[tk.w];
}

// ---------------- launch ----------------
extern "C" void kernel_launch(void* const* d_in, const int* in_sizes, int n_in,
                              void* d_out, int out_size) {
    const int*   story = (const int*)d_in[0];
    const float* q     = (const float*)d_in[1];
    const float* C     = (const float*)d_in[2];
    float* out = (float*)d_out;     // [prob_lg: B*M][u1: B*D]

    const float* C0 = C;
    const float* C1 = C + (size_t)VV * DD;
    const float* C2 = C + 2 * (size_t)VV * DD;

    // ---- hop 0 (u = q read directly; also inits g_u, dtype flag, zeros w) ----
    k_dot<true,  true,  false, false><<<2000, 128>>>(C0, q, nullptr, story);
    k_att<<<BM/256, 256>>>(story);
    k_update<<<VV/UVC, 256>>>(C1);

    // ---- hop 1 (dot also emits u1 = g_u to out) ----
    k_dot<false, true,  true,  true ><<<2000, 128>>>(C1, nullptr, out + BM, story);
    k_att<<<BM/256, 256>>>(story);
    k_update<<<VV/UVC, 256>>>(C2);

    // ---- hop 2: only logits needed (they ARE prob_lg) ----
    k_dot<false, false, false, true ><<<2000, 128>>>(C2, nullptr, nullptr, story);
    k_logits_out<<<BM/256, 256>>>(story, out);
}

// round 5
// speedup vs baseline: 1.0635x; 1.0635x over previous
#include <cuda_runtime.h>
#include <cstdint>

#define BB 16
#define DD 128
#define MM 4096
#define VV 32000
#define BM (BB*MM)

// ---------------- scratch (static device globals; no allocation) ----------------
__device__ __align__(16) float g_u[BB*DD];   // current query u  [B][D]
__device__ __align__(16) float g_t[BB*VV];   // score table t[b][v] = C_h[v].u[b]
__device__ __align__(16) float g_w[BB*VV];   // scattered (unnormalized) exp weights
__device__ float g_sum[BB];                  // softmax denominators
__device__ int g_is64;                       // story dtype flag (1 if int64)

// ---------------- helpers ----------------
__device__ __forceinline__ int4 load_toks(const int* __restrict__ story, int idx) {
    if (!g_is64) {
        return ((const int4*)story)[idx];
    } else {
        longlong4 l = ((const longlong4*)story)[idx];
        return make_int4((int)l.x, (int)l.y, (int)l.z, (int)l.w);
    }
}

__device__ __forceinline__ uint64_t packf2(float x, float y) {
    uint64_t r;
    asm("mov.b64 %0, {%1, %2};" : "=l"(r) : "f"(x), "f"(y));
    return r;
}
__device__ __forceinline__ void unpackf2(uint64_t v, float& x, float& y) {
    asm("mov.b64 {%0, %1}, %2;" : "=f"(x), "=f"(y) : "l"(v));
}
// packed dual-FMA: acc.{lo,hi} += a.{lo,hi} * b.{lo,hi}
__device__ __forceinline__ void ffma2(uint64_t& acc, uint64_t a, uint64_t b) {
    asm("fma.rn.f32x2 %0, %1, %2, %0;" : "+l"(acc) : "l"(a), "l"(b));
}

// ---------------- kernels ----------------

// t[b][v] = dot(C_h[v], u[b]) for all v,b.   Grid MUST be 2000 x 128.
// Block covers 16 rows. Warp layout:
//   rowgrp = warp>>1 selects rows [8*rowgrp, 8*rowgrp+8) of the block
//   bgrp   = warp&1  selects b in [8*bgrp, 8*bgrp+8)
//   lane: b = bgrp*8 + (lane>>2), quarter q = lane&3 -> dims [32q, 32q+32)
// Per lane per row: 8 LDS.128 (staggered, conflict-free) + 16 FFMA2 (2 chains).
// FIRST : also init g_u = uin(q) and detect story dtype
// ZERO_W: also zero g_w/g_sum for the following scatter pass
// COPY_U: block 0 additionally copies g_u (== u1) to u_out
// USE_GU: read u from g_u instead of the uin parameter
template <bool FIRST, bool ZERO_W, bool COPY_U, bool USE_GU>
__global__ void __launch_bounds__(128) k_dot(const float* __restrict__ Ch,
                                             const float* __restrict__ uin,
                                             float* __restrict__ u_out,
                                             const int* __restrict__ story) {
    if (ZERO_W) {
        int j = blockIdx.x*128 + threadIdx.x;          // 256000 threads >= 128000 float4
        if (j < BB*VV/4) ((float4*)g_w)[j] = make_float4(0.f, 0.f, 0.f, 0.f);
        if (blockIdx.x == 0 && threadIdx.x < BB) g_sum[threadIdx.x] = 0.f;
    }
    if (FIRST && blockIdx.x == 0) {
        for (int j = threadIdx.x; j < BB*DD; j += 128) g_u[j] = uin[j];
        if (threadIdx.x == 0) {
            // int64 little-endian: odd words are high words of small tokens -> 0
            int z = story[1] | story[3] | story[5] | story[7];
            g_is64 = (z == 0) ? 1 : 0;
        }
    }
    if (COPY_U && blockIdx.x == 0) {
        for (int j = threadIdx.x; j < BB*DD; j += 128) u_out[j] = g_u[j];
    }

    __shared__ ulonglong2 rowbuf[16][32];              // 16 rows x 512B = 8KB

    const int warp   = threadIdx.x >> 5;
    const int lane   = threadIdx.x & 31;
    const int rowgrp = warp >> 1;
    const int bgrp   = warp & 1;
    const int b      = bgrp*8 + (lane >> 2);
    const int q      = lane & 3;

    const int v0 = blockIdx.x * 16;

    // ---- load phase: warp w loads rows [4w, 4w+4), lane takes 16B of each row
    {
        float4 tmp[4];
        const int r0 = warp * 4;
        #pragma unroll
        for (int r = 0; r < 4; r++)
            tmp[r] = ((const float4*)(Ch + (size_t)(v0 + r0 + r) * DD))[lane];
        #pragma unroll
        for (int r = 0; r < 4; r++)
            rowbuf[r0 + r][lane] =
                make_ulonglong2(packf2(tmp[r].x, tmp[r].y), packf2(tmp[r].z, tmp[r].w));
    }

    // ---- u registers: this lane's quarter = 32 floats = 16 packed u64
    uint64_t ureg[16];
    {
        const float4* u4 = USE_GU ? (const float4*)g_u : (const float4*)uin;
        #pragma unroll
        for (int s = 0; s < 8; s++) {
            float4 uu = u4[b*32 + q*8 + s];
            ureg[2*s]   = packf2(uu.x, uu.y);
            ureg[2*s+1] = packf2(uu.z, uu.w);
        }
    }

    __syncthreads();

    // ---- compute phase: 8 rows per warp
    float tacc[8];
    const int rbase = rowgrp * 8;
    #pragma unroll
    for (int r = 0; r < 8; r++) {
        uint64_t a0 = packf2(0.f, 0.f);
        uint64_t a1 = packf2(0.f, 0.f);
        const ulonglong2* row = rowbuf[rbase + r];
        #pragma unroll
        for (int j = 0; j < 8; j++) {
            const int s = (j + q) & 7;                 // bank-stagger across quarters
            ulonglong2 c = row[q*8 + s];               // LDS.128, 8-lane broadcast
            ffma2(a0, c.x, ureg[2*s]);
            ffma2(a1, c.y, ureg[2*s+1]);
        }
        float x0, x1, x2, x3;
        unpackf2(a0, x0, x1);
        unpackf2(a1, x2, x3);
        float s = (x0 + x1) + (x2 + x3);
        s += __shfl_down_sync(0xffffffffu, s, 2);      // quarter-group reduce
        s += __shfl_down_sync(0xffffffffu, s, 1);
        tacc[r] = s;                                   // valid in q==0 lanes
    }

    // ---- store: q==0 lanes hold 8 consecutive t values -> 2 STG.128
    if (q == 0) {
        float* dst = g_t + b*VV + v0 + rbase;
        ((float4*)dst)[0] = make_float4(tacc[0], tacc[1], tacc[2], tacc[3]);
        ((float4*)dst)[1] = make_float4(tacc[4], tacc[5], tacc[6], tacc[7]);
    }
}

// Fused attention: logits -> exp (no max shift; logits are O(10) by construction)
// -> scatter unnormalized e into g_w, accumulate per-b sum via one block atomic.
__global__ void __launch_bounds__(256) k_att(const int* __restrict__ story) {
    const int i = blockIdx.x*256 + threadIdx.x;
    const int b = i >> 12;
    int4 tk = load_toks(story, i);
    const float* tb = g_t + b*VV;
    float val = tb[tk.x] + tb[tk.y] + tb[tk.z] + tb[tk.w];
    float e = __expf(val);

    float s = e;
    #pragma unroll
    for (int o = 16; o; o >>= 1) s += __shfl_xor_sync(0xffffffffu, s, o);
    __shared__ float sw[8];
    const int lane = threadIdx.x & 31, wid = threadIdx.x >> 5;
    if (lane == 0) sw[wid] = s;
    __syncthreads();
    if (threadIdx.x == 0) {
        float t = 0.f;
        #pragma unroll
        for (int k = 0; k < 8; k++) t += sw[k];
        atomicAdd(&g_sum[b], t);
    }

    float* wb = g_w + b*VV;
    atomicAdd(&wb[tk.x], e);
    atomicAdd(&wb[tk.y], e);
    atomicAdd(&wb[tk.z], e);
    atomicAdd(&wb[tk.w], e);
}

// u[b][d] += sum_v (w[b][v]/sum[b]) * C_next[v][d]
// 500 blocks x 256 threads; block covers UVC=64 vocab rows for all 16 b.
#define UVC 64
__global__ void __launch_bounds__(256) k_update(const float* __restrict__ Cn) {
    __shared__ __align__(16) float wsh[BB][UVC];
    __shared__ float sinv[BB];
    const int tid = threadIdx.x;
    const int d   = tid & 127;
    const int b0  = (tid >> 7) * 8;
    const int v0  = blockIdx.x * UVC;

    if (tid < BB) sinv[tid] = 1.0f / g_sum[tid];
    __syncthreads();
    #pragma unroll
    for (int j = tid; j < BB*UVC; j += 256) {
        int b = j >> 6, vi = j & (UVC-1);
        wsh[b][vi] = g_w[b*VV + v0 + vi] * sinv[b];
    }
    __syncthreads();

    float acc[8];
    #pragma unroll
    for (int b = 0; b < 8; b++) acc[b] = 0.f;

    const float* base = Cn + (size_t)v0 * DD + d;

    #pragma unroll 2
    for (int vi4 = 0; vi4 < UVC/4; vi4++) {
        float c0 = base[(size_t)(vi4*4 + 0) * DD];
        float c1 = base[(size_t)(vi4*4 + 1) * DD];
        float c2 = base[(size_t)(vi4*4 + 2) * DD];
        float c3 = base[(size_t)(vi4*4 + 3) * DD];
        #pragma unroll
        for (int b = 0; b < 8; b++) {
            float4 w = ((const float4*)wsh[b0 + b])[vi4];
            acc[b] += w.x*c0;
            acc[b] += w.y*c1;
            acc[b] += w.z*c2;
            acc[b] += w.w*c3;
        }
    }

    #pragma unroll
    for (int b = 0; b < 8; b++)
        atomicAdd(&g_u[(b0 + b)*DD + d], acc[b]);
}

// final-hop logits straight to output
__global__ void __launch_bounds__(256) k_logits_out(const int* __restrict__ story,
                                                    float* __restrict__ out) {
    const int i = blockIdx.x*256 + threadIdx.x;
    const int b = i >> 12;
    int4 tk = load_toks(story, i);
    const float* tb = g_t + b*VV;
    out[i] = tb[tk.x] + tb[tk.y] + tb[tk.z] + tb[tk.w];
}

// ---------------- launch ----------------
extern "C" void kernel_launch(void* const* d_in, const int* in_sizes, int n_in,
                              void* d_out, int out_size) {
    const int*   story = (const int*)d_in[0];
    const float* q     = (const float*)d_in[1];
    const float* C     = (const float*)d_in[2];
    float* out = (float*)d_out;     // [prob_lg: B*M][u1: B*D]

    const float* C0 = C;
    const float* C1 = C + (size_t)VV * DD;
    const float* C2 = C + 2 * (size_t)VV * DD;

    // ---- hop 0 (u = q read directly; also inits g_u, dtype flag, zeros w) ----
    k_dot<true,  true,  false, false><<<2000, 128>>>(C0, q, nullptr, story);
    k_att<<<BM/256, 256>>>(story);
    k_update<<<VV/UVC, 256>>>(C1);

    // ---- hop 1 (dot also emits u1 = g_u to out) ----
    k_dot<false, true,  true,  true ><<<2000, 128>>>(C1, nullptr, out + BM, story);
    k_att<<<BM/256, 256>>>(story);
    k_update<<<VV/UVC, 256>>>(C2);

    // ---- hop 2: only logits needed (they ARE prob_lg) ----
    k_dot<false, false, false, true ><<<2000, 128>>>(C2, nullptr, nullptr, story);
    k_logits_out<<<BM/256, 256>>>(story, out);
}

// round 6
// speedup vs baseline: 1.0682x; 1.0045x over previous
#include <cuda_runtime.h>
#include <cstdint>

#define BB 16
#define DD 128
#define MM 4096
#define VV 32000
#define BM (BB*MM)

// ---------------- scratch (static device globals; no allocation) ----------------
__device__ __align__(16) float g_u[BB*DD];   // current query u  [B][D]
__device__ __align__(16) float g_t[BB*VV];   // score table t[b][v] = C_h[v].u[b]
__device__ __align__(16) float g_w[BB*VV];   // scattered (unnormalized) exp weights
__device__ float g_sum[BB];                  // softmax denominators
__device__ int g_is64;                       // story dtype flag (1 if int64)

// ---------------- helpers ----------------
__device__ __forceinline__ int4 load_toks(const int* __restrict__ story, int idx) {
    if (!g_is64) {
        return ((const int4*)story)[idx];
    } else {
        longlong4 l = ((const longlong4*)story)[idx];
        return make_int4((int)l.x, (int)l.y, (int)l.z, (int)l.w);
    }
}

__device__ __forceinline__ uint64_t packf2(float x, float y) {
    uint64_t r;
    asm("mov.b64 %0, {%1, %2};" : "=l"(r) : "f"(x), "f"(y));
    return r;
}
__device__ __forceinline__ void unpackf2(uint64_t v, float& x, float& y) {
    asm("mov.b64 {%0, %1}, %2;" : "=f"(x), "=f"(y) : "l"(v));
}
// packed dual-FMA: acc.{lo,hi} += a.{lo,hi} * b.{lo,hi}
__device__ __forceinline__ void ffma2(uint64_t& acc, uint64_t a, uint64_t b) {
    asm("fma.rn.f32x2 %0, %1, %2, %0;" : "+l"(acc) : "l"(a), "l"(b));
}

// ---------------- kernels ----------------

// t[b][v] = dot(C_h[v], u[b]) for all v,b.   Grid MUST be 2000 x 128.
// Tile = 16 rows staged into smem via cp.async (no register staging -> low regs
// -> 8 blocks/SM resident; DRAM latency carried by the async queue and covered
// by other resident blocks' compute).
// Warp layout (unchanged from R5):
//   rowgrp = warp>>1 -> rows [8*rowgrp, 8*rowgrp+8) ; bgrp = warp&1 -> b range
//   lane: b = bgrp*8 + (lane>>2), quarter q = lane&3 -> dims [32q, 32q+32)
template <bool FIRST, bool ZERO_W, bool COPY_U, bool USE_GU>
__global__ void __launch_bounds__(128) k_dot(const float* __restrict__ Ch,
                                             const float* __restrict__ uin,
                                             float* __restrict__ u_out,
                                             const int* __restrict__ story) {
    if (ZERO_W) {
        int j = blockIdx.x*128 + threadIdx.x;          // 256000 threads >= 128000 float4
        if (j < BB*VV/4) ((float4*)g_w)[j] = make_float4(0.f, 0.f, 0.f, 0.f);
        if (blockIdx.x == 0 && threadIdx.x < BB) g_sum[threadIdx.x] = 0.f;
    }
    if (FIRST && blockIdx.x == 0) {
        for (int j = threadIdx.x; j < BB*DD; j += 128) g_u[j] = uin[j];
        if (threadIdx.x == 0) {
            // int64 little-endian: odd words are high words of small tokens -> 0
            int z = story[1] | story[3] | story[5] | story[7];
            g_is64 = (z == 0) ? 1 : 0;
        }
    }
    if (COPY_U && blockIdx.x == 0) {
        for (int j = threadIdx.x; j < BB*DD; j += 128) u_out[j] = g_u[j];
    }

    __shared__ __align__(16) ulonglong2 rowbuf[16][32];   // 16 rows x 512B = 8KB

    const int tid  = threadIdx.x;
    const int warp = tid >> 5;
    const int lane = tid & 31;
    const int rowgrp = warp >> 1;
    const int bgrp   = warp & 1;
    const int b      = bgrp*8 + (lane >> 2);
    const int q      = lane & 3;

    const int v0 = blockIdx.x * 16;

    // ---- async tile load: 512 chunks of 16B, 4 per thread, no register staging
    {
        uint32_t sbase = (uint32_t)__cvta_generic_to_shared(rowbuf);
        #pragma unroll
        for (int k = 0; k < 4; k++) {
            const int c   = tid + k*128;                 // chunk id
            const int row = c >> 5, col = c & 31;
            const float4* gp = (const float4*)(Ch + (size_t)(v0 + row) * DD) + col;
            uint32_t sp = sbase + c*16;
            asm volatile("cp.async.cg.shared.global [%0], [%1], 16;\n"
                         :: "r"(sp), "l"(gp));
        }
        asm volatile("cp.async.commit_group;\n");
    }

    // ---- u registers (overlaps with the async loads): quarter = 32 floats
    uint64_t ureg[16];
    {
        const float4* u4 = USE_GU ? (const float4*)g_u : (const float4*)uin;
        #pragma unroll
        for (int s = 0; s < 8; s++) {
            float4 uu = u4[b*32 + q*8 + s];
            ureg[2*s]   = packf2(uu.x, uu.y);
            ureg[2*s+1] = packf2(uu.z, uu.w);
        }
    }

    asm volatile("cp.async.wait_group 0;\n" ::: "memory");
    __syncthreads();

    // ---- compute phase: 8 rows per warp
    float tacc[8];
    const int rbase = rowgrp * 8;
    #pragma unroll
    for (int r = 0; r < 8; r++) {
        uint64_t a0 = packf2(0.f, 0.f);
        uint64_t a1 = packf2(0.f, 0.f);
        const ulonglong2* row = rowbuf[rbase + r];
        #pragma unroll
        for (int j = 0; j < 8; j++) {
            const int s = (j + q) & 7;                 // bank-stagger across quarters
            ulonglong2 c = row[q*8 + s];               // LDS.128, 8-lane broadcast
            ffma2(a0, c.x, ureg[2*s]);
            ffma2(a1, c.y, ureg[2*s+1]);
        }
        float x0, x1, x2, x3;
        unpackf2(a0, x0, x1);
        unpackf2(a1, x2, x3);
        float s = (x0 + x1) + (x2 + x3);
        s += __shfl_down_sync(0xffffffffu, s, 2);      // quarter-group reduce
        s += __shfl_down_sync(0xffffffffu, s, 1);
        tacc[r] = s;                                   // valid in q==0 lanes
    }

    // ---- store: q==0 lanes hold 8 consecutive t values -> 2 STG.128
    if (q == 0) {
        float* dst = g_t + b*VV + v0 + rbase;
        ((float4*)dst)[0] = make_float4(tacc[0], tacc[1], tacc[2], tacc[3]);
        ((float4*)dst)[1] = make_float4(tacc[4], tacc[5], tacc[6], tacc[7]);
    }
}

// Fused attention: logits -> exp (no max shift; logits are O(10) by construction)
// -> scatter unnormalized e into g_w, accumulate per-b sum via one block atomic.
__global__ void __launch_bounds__(256) k_att(const int* __restrict__ story) {
    const int i = blockIdx.x*256 + threadIdx.x;
    const int b = i >> 12;
    int4 tk = load_toks(story, i);
    const float* tb = g_t + b*VV;
    float val = tb[tk.x] + tb[tk.y] + tb[tk.z] + tb[tk.w];
    float e = __expf(val);

    float s = e;
    #pragma unroll
    for (int o = 16; o; o >>= 1) s += __shfl_xor_sync(0xffffffffu, s, o);
    __shared__ float sw[8];
    const int lane = threadIdx.x & 31, wid = threadIdx.x >> 5;
    if (lane == 0) sw[wid] = s;
    __syncthreads();
    if (threadIdx.x == 0) {
        float t = 0.f;
        #pragma unroll
        for (int k = 0; k < 8; k++) t += sw[k];
        atomicAdd(&g_sum[b], t);
    }

    float* wb = g_w + b*VV;
    atomicAdd(&wb[tk.x], e);
    atomicAdd(&wb[tk.y], e);
    atomicAdd(&wb[tk.z], e);
    atomicAdd(&wb[tk.w], e);
}

// u[b][d] += sum_v (w[b][v]/sum[b]) * C_next[v][d]
// 500 blocks x 256 threads; block covers UVC=64 vocab rows for all 16 b.
#define UVC 64
__global__ void __launch_bounds__(256) k_update(const float* __restrict__ Cn) {
    __shared__ __align__(16) float wsh[BB][UVC];
    __shared__ float sinv[BB];
    const int tid = threadIdx.x;
    const int d   = tid & 127;
    const int b0  = (tid >> 7) * 8;
    const int v0  = blockIdx.x * UVC;

    if (tid < BB) sinv[tid] = 1.0f / g_sum[tid];
    __syncthreads();
    #pragma unroll
    for (int j = tid; j < BB*UVC; j += 256) {
        int b = j >> 6, vi = j & (UVC-1);
        wsh[b][vi] = g_w[b*VV + v0 + vi] * sinv[b];
    }
    __syncthreads();

    float acc[8];
    #pragma unroll
    for (int b = 0; b < 8; b++) acc[b] = 0.f;

    const float* base = Cn + (size_t)v0 * DD + d;

    #pragma unroll 2
    for (int vi4 = 0; vi4 < UVC/4; vi4++) {
        float c0 = base[(size_t)(vi4*4 + 0) * DD];
        float c1 = base[(size_t)(vi4*4 + 1) * DD];
        float c2 = base[(size_t)(vi4*4 + 2) * DD];
        float c3 = base[(size_t)(vi4*4 + 3) * DD];
        #pragma unroll
        for (int b = 0; b < 8; b++) {
            float4 w = ((const float4*)wsh[b0 + b])[vi4];
            acc[b] += w.x*c0;
            acc[b] += w.y*c1;
            acc[b] += w.z*c2;
            acc[b] += w.w*c3;
        }
    }

    #pragma unroll
    for (int b = 0; b < 8; b++)
        atomicAdd(&g_u[(b0 + b)*DD + d], acc[b]);
}

// final-hop logits straight to output
__global__ void __launch_bounds__(256) k_logits_out(const int* __restrict__ story,
                                                    float* __restrict__ out) {
    const int i = blockIdx.x*256 + threadIdx.x;
    const int b = i >> 12;
    int4 tk = load_toks(story, i);
    const float* tb = g_t + b*VV;
    out[i] = tb[tk.x] + tb[tk.y] + tb[tk.z] + tb[tk.w];
}

// ---------------- launch ----------------
extern "C" void kernel_launch(void* const* d_in, const int* in_sizes, int n_in,
                              void* d_out, int out_size) {
    const int*   story = (const int*)d_in[0];
    const float* q     = (const float*)d_in[1];
    const float* C     = (const float*)d_in[2];
    float* out = (float*)d_out;     // [prob_lg: B*M][u1: B*D]

    const float* C0 = C;
    const float* C1 = C + (size_t)VV * DD;
    const float* C2 = C + 2 * (size_t)VV * DD;

    // ---- hop 0 (u = q read directly; also inits g_u, dtype flag, zeros w) ----
    k_dot<true,  true,  false, false><<<2000, 128>>>(C0, q, nullptr, story);
    k_att<<<BM/256, 256>>>(story);
    k_update<<<VV/UVC, 256>>>(C1);

    // ---- hop 1 (dot also emits u1 = g_u to out) ----
    k_dot<false, true,  true,  true ><<<2000, 128>>>(C1, nullptr, out + BM, story);
    k_att<<<BM/256, 256>>>(story);
    k_update<<<VV/UVC, 256>>>(C2);

    // ---- hop 2: only logits needed (they ARE prob_lg) ----
    k_dot<false, false, false, true ><<<2000, 128>>>(C2, nullptr, nullptr, story);
    k_logits_out<<<BM/256, 256>>>(story, out);
}

// round 7
// speedup vs baseline: 1.3345x; 1.2493x over previous
#include <cuda_runtime.h>
#include <cstdint>

#define BB 16
#define DD 128
#define MM 4096
#define VV 32000
#define BM (BB*MM)

// ---------------- scratch (static device globals; no allocation) ----------------
__device__ __align__(16) float g_u[BB*DD];   // current query u  [B][D]
__device__ __align__(16) float g_t[BB*VV];   // score table t[b][v] = C_h[v].u[b]
__device__ __align__(16) float g_w[BB*VV];   // scattered (unnormalized) exp weights
__device__ float g_sum[BB];                  // softmax denominators
__device__ int g_is64;                       // story dtype flag (1 if int64)

// ---------------- helpers ----------------
__device__ __forceinline__ int4 load_toks(const int* __restrict__ story, int idx) {
    if (!g_is64) {
        return ((const int4*)story)[idx];
    } else {
        longlong4 l = ((const longlong4*)story)[idx];
        return make_int4((int)l.x, (int)l.y, (int)l.z, (int)l.w);
    }
}

__device__ __forceinline__ uint64_t packf2(float x, float y) {
    uint64_t r;
    asm("mov.b64 %0, {%1, %2};" : "=l"(r) : "f"(x), "f"(y));
    return r;
}
__device__ __forceinline__ void unpackf2(uint64_t v, float& x, float& y) {
    asm("mov.b64 {%0, %1}, %2;" : "=f"(x), "=f"(y) : "l"(v));
}
// packed dual-FMA: acc.{lo,hi} += a.{lo,hi} * b.{lo,hi}
__device__ __forceinline__ void ffma2(uint64_t& acc, uint64_t a, uint64_t b) {
    asm("fma.rn.f32x2 %0, %1, %2, %0;" : "+l"(acc) : "l"(a), "l"(b));
}

// ---------------- kernels ----------------

#define TILES 4          // tiles per block
#define TR    16         // rows per tile

// t[b][v] = dot(C_h[v], u[b]) for all v,b.   Grid MUST be 500 x 128.
// Each block: 4 tiles of 16 rows, double-buffered cp.async pipeline
// (tile t+2 loads while tile t computes). Warp layout per tile (as R5):
//   rowgrp = warp>>1 -> rows [8*rowgrp, 8*rowgrp+8) ; bgrp = warp&1 -> b range
//   lane: b = bgrp*8 + (lane>>2), quarter q = lane&3 -> dims [32q, 32q+32)
// Compute interleaves row pairs (4 independent FFMA2 chains, 2 indep LDS).
template <bool FIRST, bool ZERO_W, bool COPY_U, bool USE_GU>
__global__ void __launch_bounds__(128) k_dot(const float* __restrict__ Ch,
                                             const float* __restrict__ uin,
                                             float* __restrict__ u_out,
                                             const int* __restrict__ story) {
    if (ZERO_W) {
        const int nt = gridDim.x * 128;                // 64000 threads
        for (int j = blockIdx.x*128 + threadIdx.x; j < BB*VV/4; j += nt)
            ((float4*)g_w)[j] = make_float4(0.f, 0.f, 0.f, 0.f);
        if (blockIdx.x == 0 && threadIdx.x < BB) g_sum[threadIdx.x] = 0.f;
    }
    if (FIRST && blockIdx.x == 0) {
        for (int j = threadIdx.x; j < BB*DD; j += 128) g_u[j] = uin[j];
        if (threadIdx.x == 0) {
            // int64 little-endian: odd words are high words of small tokens -> 0
            int z = story[1] | story[3] | story[5] | story[7];
            g_is64 = (z == 0) ? 1 : 0;
        }
    }
    if (COPY_U && blockIdx.x == 0) {
        for (int j = threadIdx.x; j < BB*DD; j += 128) u_out[j] = g_u[j];
    }

    __shared__ __align__(16) ulonglong2 rowbuf[2][TR][32];  // 2 x 8KB buffers

    const int tid  = threadIdx.x;
    const int warp = tid >> 5;
    const int lane = tid & 31;
    const int rowgrp = warp >> 1;
    const int bgrp   = warp & 1;
    const int b      = bgrp*8 + (lane >> 2);
    const int q      = lane & 3;
    const int rbase  = rowgrp * 8;

    const int base_v = blockIdx.x * (TILES*TR);

    // precomputed per-thread load coordinates (4 x 16B chunks per tile)
    const int c_row0 = tid >> 5;          // rows tid>>5 + {0,4,8,12}... see loop
    const int c_col  = tid & 31;

    // ---- async tile loader: tile tt -> buffer buf
    auto load_tile = [&](int buf, int tt) {
        uint32_t sbase = (uint32_t)__cvta_generic_to_shared(&rowbuf[buf][0][0]);
        const float* src = Ch + (size_t)(base_v + tt*TR) * DD;
        #pragma unroll
        for (int k = 0; k < 4; k++) {
            const int row = c_row0 + k*4;
            const float4* gp = (const float4*)(src + (size_t)row * DD) + c_col;
            uint32_t sp = sbase + (row*32 + c_col)*16;
            asm volatile("cp.async.cg.shared.global [%0], [%1], 16;\n"
                         :: "r"(sp), "l"(gp));
        }
        asm volatile("cp.async.commit_group;\n");
    };

    load_tile(0, 0);

    // ---- u registers (overlap with first load): quarter = 32 floats
    uint64_t ureg[16];
    {
        const float4* u4 = USE_GU ? (const float4*)g_u : (const float4*)uin;
        #pragma unroll
        for (int s = 0; s < 8; s++) {
            float4 uu = u4[b*32 + q*8 + s];
            ureg[2*s]   = packf2(uu.x, uu.y);
            ureg[2*s+1] = packf2(uu.z, uu.w);
        }
    }

    load_tile(1, 1);

    #pragma unroll
    for (int t = 0; t < TILES; t++) {
        const int buf = t & 1;
        if (t < TILES - 1) asm volatile("cp.async.wait_group 1;\n" ::: "memory");
        else               asm volatile("cp.async.wait_group 0;\n" ::: "memory");
        __syncthreads();

        // ---- compute 8 rows as 4 interleaved row-pairs
        float tacc[8];
        #pragma unroll
        for (int rp = 0; rp < 4; rp++) {
            uint64_t a00 = packf2(0.f, 0.f), a01 = packf2(0.f, 0.f);
            uint64_t a10 = packf2(0.f, 0.f), a11 = packf2(0.f, 0.f);
            const ulonglong2* row0 = rowbuf[buf][rbase + 2*rp];
            const ulonglong2* row1 = rowbuf[buf][rbase + 2*rp + 1];
            #pragma unroll
            for (int j = 0; j < 8; j++) {
                const int s = (j + q) & 7;             // bank-stagger across quarters
                ulonglong2 c0 = row0[q*8 + s];         // two independent LDS.128
                ulonglong2 c1 = row1[q*8 + s];
                ffma2(a00, c0.x, ureg[2*s]);
                ffma2(a10, c1.x, ureg[2*s]);
                ffma2(a01, c0.y, ureg[2*s+1]);
                ffma2(a11, c1.y, ureg[2*s+1]);
            }
            float x0, x1, x2, x3, y0, y1, y2, y3;
            unpackf2(a00, x0, x1); unpackf2(a01, x2, x3);
            unpackf2(a10, y0, y1); unpackf2(a11, y2, y3);
            float s0 = (x0 + x1) + (x2 + x3);
            float s1 = (y0 + y1) + (y2 + y3);
            s0 += __shfl_down_sync(0xffffffffu, s0, 2);
            s1 += __shfl_down_sync(0xffffffffu, s1, 2);
            s0 += __shfl_down_sync(0xffffffffu, s0, 1);
            s1 += __shfl_down_sync(0xffffffffu, s1, 1);
            tacc[2*rp]   = s0;
            tacc[2*rp+1] = s1;
        }

        // ---- store: q==0 lanes hold 8 consecutive t values -> 2 STG.128
        if (q == 0) {
            float* dst = g_t + b*VV + base_v + t*TR + rbase;
            ((float4*)dst)[0] = make_float4(tacc[0], tacc[1], tacc[2], tacc[3]);
            ((float4*)dst)[1] = make_float4(tacc[4], tacc[5], tacc[6], tacc[7]);
        }

        __syncthreads();                               // buffer free for reuse
        if (t + 2 < TILES) load_tile(buf, t + 2);
    }
}

// Fused attention: logits -> exp (no max shift; logits are O(10) by construction)
// -> scatter unnormalized e into g_w, accumulate per-b sum via one block atomic.
__global__ void __launch_bounds__(256) k_att(const int* __restrict__ story) {
    const int i = blockIdx.x*256 + threadIdx.x;
    const int b = i >> 12;
    int4 tk = load_toks(story, i);
    const float* tb = g_t + b*VV;
    float val = tb[tk.x] + tb[tk.y] + tb[tk.z] + tb[tk.w];
    float e = __expf(val);

    float s = e;
    #pragma unroll
    for (int o = 16; o; o >>= 1) s += __shfl_xor_sync(0xffffffffu, s, o);
    __shared__ float sw[8];
    const int lane = threadIdx.x & 31, wid = threadIdx.x >> 5;
    if (lane == 0) sw[wid] = s;
    __syncthreads();
    if (threadIdx.x == 0) {
        float t = 0.f;
        #pragma unroll
        for (int k = 0; k < 8; k++) t += sw[k];
        atomicAdd(&g_sum[b], t);
    }

    float* wb = g_w + b*VV;
    atomicAdd(&wb[tk.x], e);
    atomicAdd(&wb[tk.y], e);
    atomicAdd(&wb[tk.z], e);
    atomicAdd(&wb[tk.w], e);
}

// u[b][d] += sum_v (w[b][v]/sum[b]) * C_next[v][d]
// 500 blocks x 256 threads; block covers UVC=64 vocab rows for all 16 b.
#define UVC 64
__global__ void __launch_bounds__(256) k_update(const float* __restrict__ Cn) {
    __shared__ __align__(16) float wsh[BB][UVC];
    __shared__ float sinv[BB];
    const int tid = threadIdx.x;
    const int d   = tid & 127;
    const int b0  = (tid >> 7) * 8;
    const int v0  = blockIdx.x * UVC;

    if (tid < BB) sinv[tid] = 1.0f / g_sum[tid];
    __syncthreads();
    #pragma unroll
    for (int j = tid; j < BB*UVC; j += 256) {
        int b = j >> 6, vi = j & (UVC-1);
        wsh[b][vi] = g_w[b*VV + v0 + vi] * sinv[b];
    }
    __syncthreads();

    float acc[8];
    #pragma unroll
    for (int b = 0; b < 8; b++) acc[b] = 0.f;

    const float* base = Cn + (size_t)v0 * DD + d;

    #pragma unroll 2
    for (int vi4 = 0; vi4 < UVC/4; vi4++) {
        float c0 = base[(size_t)(vi4*4 + 0) * DD];
        float c1 = base[(size_t)(vi4*4 + 1) * DD];
        float c2 = base[(size_t)(vi4*4 + 2) * DD];
        float c3 = base[(size_t)(vi4*4 + 3) * DD];
        #pragma unroll
        for (int b = 0; b < 8; b++) {
            float4 w = ((const float4*)wsh[b0 + b])[vi4];
            acc[b] += w.x*c0;
            acc[b] += w.y*c1;
            acc[b] += w.z*c2;
            acc[b] += w.w*c3;
        }
    }

    #pragma unroll
    for (int b = 0; b < 8; b++)
        atomicAdd(&g_u[(b0 + b)*DD + d], acc[b]);
}

// final-hop logits straight to output
__global__ void __launch_bounds__(256) k_logits_out(const int* __restrict__ story,
                                                    float* __restrict__ out) {
    const int i = blockIdx.x*256 + threadIdx.x;
    const int b = i >> 12;
    int4 tk = load_toks(story, i);
    const float* tb = g_t + b*VV;
    out[i] = tb[tk.x] + tb[tk.y] + tb[tk.z] + tb[tk.w];
}

// ---------------- launch ----------------
extern "C" void kernel_launch(void* const* d_in, const int* in_sizes, int n_in,
                              void* d_out, int out_size) {
    const int*   story = (const int*)d_in[0];
    const float* q     = (const float*)d_in[1];
    const float* C     = (const float*)d_in[2];
    float* out = (float*)d_out;     // [prob_lg: B*M][u1: B*D]

    const float* C0 = C;
    const float* C1 = C + (size_t)VV * DD;
    const float* C2 = C + 2 * (size_t)VV * DD;

    // ---- hop 0 (u = q read directly; also inits g_u, dtype flag, zeros w) ----
    k_dot<true,  true,  false, false><<<500, 128>>>(C0, q, nullptr, story);
    k_att<<<BM/256, 256>>>(story);
    k_update<<<VV/UVC, 256>>>(C1);

    // ---- hop 1 (dot also emits u1 = g_u to out) ----
    k_dot<false, true,  true,  true ><<<500, 128>>>(C1, nullptr, out + BM, story);
    k_att<<<BM/256, 256>>>(story);
    k_update<<<VV/UVC, 256>>>(C2);

    // ---- hop 2: only logits needed (they ARE prob_lg) ----
    k_dot<false, false, false, true ><<<500, 128>>>(C2, nullptr, nullptr, story);
    k_logits_out<<<BM/256, 256>>>(story, out);
}